// round 7
// baseline (speedup 1.0000x reference)
#include <cuda_runtime.h>
#include <cuda_bf16.h>
#include <cstdint>

// Masked attention B=2 H=12 S=2048 D=64 fp32.
// R6: split-K=2 flash attention (768 CTAs, partial softmax merge kernel),
// Q de-hoisted to persistent smem (no register spills),
// mma.sync m16n8k16 bf16 hi/lo split (3 MMAs/GEMM), cp.async double buffering.

#define BATCH 2
#define HN 12
#define SLEN 2048
#define DH 64
#define BQ 128
#define BK 64
#define NSPLIT 2
#define KHALF (SLEN / NSPLIT)          // 1024
#define NT_HALF (KHALF / BK)           // 16 tiles per CTA
#define NTH 128

#define ROWB 144
#define PLANEB 9216                    // 64 rows * 144B
#define BUFB (4 * PLANEB)              // KH,KL,VH,VL
#define QREGB 36864                    // QH+QL, 128 rows each
#define SMEM_BYTES (QREGB + 2 * BUFB)  // 110592

#define NELEM (BATCH * HN * SLEN * DH) // 6291456
#define NROWS (BATCH * HN * SLEN)      // 49152

__device__ __nv_bfloat16 g_QH[NELEM], g_QL[NELEM];
__device__ __nv_bfloat16 g_KH[NELEM], g_KL[NELEM];
__device__ __nv_bfloat16 g_VTH[NELEM], g_VTL[NELEM];   // [bh][d][k]
__device__ uint32_t g_MB[BATCH * SLEN * (SLEN / 32)];
__device__ float  g_OP0[NELEM], g_OP1[NELEM];          // unnormalized partial O
__device__ float2 g_ML0[NROWS], g_ML1[NROWS];          // (m, l) per row per half

__device__ __forceinline__ uint32_t smem_u32(const void* p) {
    uint32_t a;
    asm("{ .reg .u64 t; cvta.to.shared.u64 t, %1; cvt.u32.u64 %0, t; }"
        : "=r"(a) : "l"(p));
    return a;
}
__device__ __forceinline__ uint32_t pack_bf(float lo, float hi) {
    uint32_t r;
    asm("cvt.rn.satfinite.bf16x2.f32 %0, %1, %2;" : "=r"(r) : "f"(hi), "f"(lo));
    return r;
}
__device__ __forceinline__ uint2 split2(float a, float b) {
    uint32_t hw = pack_bf(a, b);
    float ha = __uint_as_float(hw << 16);
    float hb = __uint_as_float(hw & 0xffff0000u);
    return make_uint2(hw, pack_bf(a - ha, b - hb));
}
__device__ __forceinline__ void mma_bf16(float* d,
                                         uint32_t a0, uint32_t a1, uint32_t a2, uint32_t a3,
                                         uint32_t b0, uint32_t b1) {
    asm volatile("mma.sync.aligned.m16n8k16.row.col.f32.bf16.bf16.f32 "
                 "{%0,%1,%2,%3},{%4,%5,%6,%7},{%8,%9},{%0,%1,%2,%3};"
                 : "+f"(d[0]), "+f"(d[1]), "+f"(d[2]), "+f"(d[3])
                 : "r"(a0), "r"(a1), "r"(a2), "r"(a3), "r"(b0), "r"(b1));
}
__device__ __forceinline__ void ldsm4(uint32_t& r0, uint32_t& r1,
                                      uint32_t& r2, uint32_t& r3, uint32_t addr) {
    asm volatile("ldmatrix.sync.aligned.m8n8.x4.shared.b16 {%0,%1,%2,%3}, [%4];"
                 : "=r"(r0), "=r"(r1), "=r"(r2), "=r"(r3) : "r"(addr));
}
__device__ __forceinline__ void cp16(uint32_t dst, const void* src) {
    asm volatile("cp.async.cg.shared.global [%0], [%1], 16;"
                 :: "r"(dst), "l"(src) : "memory");
}
#define CP_COMMIT() asm volatile("cp.async.commit_group;" ::: "memory")
#define CP_WAIT0()  asm volatile("cp.async.wait_group 0;" ::: "memory")
#define CP_WAIT1()  asm volatile("cp.async.wait_group 1;" ::: "memory")

// ---------------- pre-pass kernels ----------------

__global__ void __launch_bounds__(256)
prep_qk(const float* __restrict__ Q, const float* __restrict__ K)
{
    const size_t i = ((size_t)blockIdx.x * 256 + threadIdx.x) * 4;
    float4 q = *reinterpret_cast<const float4*>(Q + i);
    uint2 a = split2(q.x, q.y), b = split2(q.z, q.w);
    *reinterpret_cast<uint2*>(&g_QH[i]) = make_uint2(a.x, b.x);
    *reinterpret_cast<uint2*>(&g_QL[i]) = make_uint2(a.y, b.y);
    float4 k = *reinterpret_cast<const float4*>(K + i);
    a = split2(k.x, k.y); b = split2(k.z, k.w);
    *reinterpret_cast<uint2*>(&g_KH[i]) = make_uint2(a.x, b.x);
    *reinterpret_cast<uint2*>(&g_KL[i]) = make_uint2(a.y, b.y);
}

__global__ void __launch_bounds__(256)
prep_vt(const float* __restrict__ V)
{
    __shared__ float vt[64][65];
    const int tid = threadIdx.x;
    const int bhh = blockIdx.y;
    const int k0 = blockIdx.x * 64;
    {
        const int kk = tid >> 2, c0 = (tid & 3) * 16;
        const float* src = V + ((size_t)bhh * SLEN + k0 + kk) * DH + c0;
#pragma unroll
        for (int i = 0; i < 4; i++) {
            float4 v = *reinterpret_cast<const float4*>(src + 4 * i);
            vt[c0 + 4 * i + 0][kk] = v.x;
            vt[c0 + 4 * i + 1][kk] = v.y;
            vt[c0 + 4 * i + 2][kk] = v.z;
            vt[c0 + 4 * i + 3][kk] = v.w;
        }
    }
    __syncthreads();
    {
        const int d = tid >> 2, kc = (tid & 3) * 16;
        uint32_t hw[8], lw[8];
#pragma unroll
        for (int j = 0; j < 8; j++) {
            uint2 s2 = split2(vt[d][kc + 2 * j], vt[d][kc + 2 * j + 1]);
            hw[j] = s2.x; lw[j] = s2.y;
        }
        const size_t oi = ((size_t)bhh * DH + d) * SLEN + k0 + kc;
        *reinterpret_cast<uint4*>(&g_VTH[oi])     = make_uint4(hw[0], hw[1], hw[2], hw[3]);
        *reinterpret_cast<uint4*>(&g_VTH[oi + 8]) = make_uint4(hw[4], hw[5], hw[6], hw[7]);
        *reinterpret_cast<uint4*>(&g_VTL[oi])     = make_uint4(lw[0], lw[1], lw[2], lw[3]);
        *reinterpret_cast<uint4*>(&g_VTL[oi + 8]) = make_uint4(lw[4], lw[5], lw[6], lw[7]);
    }
}

__global__ void __launch_bounds__(256)
prep_mask(const int* __restrict__ M)
{
    const int wg = blockIdx.x * 8 + (threadIdx.x >> 5);
    const int lane = threadIdx.x & 31;
    int v = M[(size_t)wg * 32 + lane];
    uint32_t bits = __ballot_sync(0xffffffffu, v != 0);
    if (lane == 0) g_MB[wg] = bits;
}

// ---------------- main attention kernel (one K-half per CTA) ----------------

__global__ void __launch_bounds__(NTH, 2)
attn_mma_kernel()
{
    extern __shared__ uint32_t smw[];
    const uint32_t smb = smem_u32(smw);

    const int tid  = threadIdx.x;
    const int lane = tid & 31;
    const int w    = tid >> 5;
    const int g    = lane >> 2;
    const int qd   = lane & 3;

    const int b    = blockIdx.z >> 1;
    const int half = blockIdx.z & 1;
    const int h    = blockIdx.y;
    const int q0   = blockIdx.x * BQ;
    const int bh   = b * HN + h;
    const int kbase = half * KHALF;

    const uint32_t offA = (uint32_t)(((lane & 7) + ((lane >> 3) & 1) * 8) * ROWB
                                     + (lane >> 4) * 16);
    const uint32_t offB = (uint32_t)(((lane & 7) + (lane >> 4) * 8) * ROWB
                                     + ((lane >> 3) & 1) * 16);

    // ---- prologue: Q hi/lo planes -> persistent smem region [0, QREGB) ----
    {
        const int col = tid & 7;
#pragma unroll
        for (int i = 0; i < 16; i++) {
            const int c = tid + NTH * i;
            const int plane = c >> 10;
            const int r2 = (c >> 3) & 127;
            const __nv_bfloat16* src = (plane ? g_QL : g_QH)
                + ((size_t)bh * SLEN + q0 + r2) * DH + col * 8;
            cp16(smb + (uint32_t)(plane * 18432 + r2 * ROWB + col * 16), src);
        }
        CP_COMMIT();
    }

    const uint32_t* mrow[4];
#pragma unroll
    for (int r = 0; r < 4; r++)
        mrow[r] = g_MB + ((size_t)b * SLEN + q0 + 32 * w + g + 8 * r) * (SLEN / 32);

    const __nv_bfloat16* KHb = g_KH + (size_t)bh * SLEN * DH;
    const __nv_bfloat16* KLb = g_KL + (size_t)bh * SLEN * DH;
    const __nv_bfloat16* VHb = g_VTH + (size_t)bh * DH * SLEN;
    const __nv_bfloat16* VLb = g_VTL + (size_t)bh * DH * SLEN;

    // prefetch tile 0
    {
        const int col = tid & 7;
#pragma unroll
        for (int i = 0; i < 16; i++) {
            const int p = i >> 2;
            const int row = (i & 3) * 16 + (tid >> 3);
            const __nv_bfloat16* src =
                (p == 0) ? KHb + (size_t)(kbase + row) * DH + col * 8 :
                (p == 1) ? KLb + (size_t)(kbase + row) * DH + col * 8 :
                (p == 2) ? VHb + (size_t)row * SLEN + kbase + col * 8 :
                           VLb + (size_t)row * SLEN + kbase + col * 8;
            cp16(smb + (uint32_t)(QREGB + p * PLANEB + row * ROWB + col * 16), src);
        }
        CP_COMMIT();
    }

    float s[2][8][4];
    float o[2][8][4] = {};
    float mx[4] = {-1e30f, -1e30f, -1e30f, -1e30f};
    float ls[4] = {};

#pragma unroll 1
    for (int t = 0; t < NT_HALF; t++) {
        const int k0 = kbase + t * BK;
        const uint32_t bufc = smb + (uint32_t)(QREGB + (t & 1) * BUFB);

        if (t + 1 < NT_HALF) {
            const uint32_t bufn = smb + (uint32_t)(QREGB + ((t + 1) & 1) * BUFB);
            const int kn = k0 + BK;
            const int col = tid & 7;
#pragma unroll
            for (int i = 0; i < 16; i++) {
                const int p = i >> 2;
                const int row = (i & 3) * 16 + (tid >> 3);
                const __nv_bfloat16* src =
                    (p == 0) ? KHb + (size_t)(kn + row) * DH + col * 8 :
                    (p == 1) ? KLb + (size_t)(kn + row) * DH + col * 8 :
                    (p == 2) ? VHb + (size_t)row * SLEN + kn + col * 8 :
                               VLb + (size_t)row * SLEN + kn + col * 8;
                cp16(bufn + (uint32_t)(p * PLANEB + row * ROWB + col * 16), src);
            }
            CP_COMMIT();
            CP_WAIT1();
        } else {
            CP_WAIT0();
        }

        uint32_t mw[4][2];
#pragma unroll
        for (int r = 0; r < 4; r++) {
            mw[r][0] = mrow[r][(k0 >> 5)];
            mw[r][1] = mrow[r][(k0 >> 5) + 1];
        }
        __syncthreads();

        // ---- MMA1: S = Qh*Kh + Qh*Kl + Ql*Kh (Q fragments from smem) ----
#pragma unroll
        for (int m = 0; m < 2; m++)
#pragma unroll
            for (int jn = 0; jn < 8; jn++)
#pragma unroll
                for (int e = 0; e < 4; e++) s[m][jn][e] = 0.0f;

#pragma unroll
        for (int kc = 0; kc < 4; kc++) {
            uint32_t qh[2][4], ql[2][4];
#pragma unroll
            for (int m = 0; m < 2; m++) {
                const uint32_t qa = smb + (uint32_t)((32 * w + 16 * m) * ROWB + kc * 32) + offA;
                ldsm4(qh[m][0], qh[m][1], qh[m][2], qh[m][3], qa);
                ldsm4(ql[m][0], ql[m][1], ql[m][2], ql[m][3], qa + 18432);
            }
#pragma unroll
            for (int jp = 0; jp < 4; jp++) {
                const uint32_t ad = bufc + (uint32_t)(jp * 16 * ROWB + kc * 32) + offB;
                uint32_t h0, h1, h2, h3, l0, l1, l2, l3;
                ldsm4(h0, h1, h2, h3, ad);
                ldsm4(l0, l1, l2, l3, ad + PLANEB);
#pragma unroll
                for (int m = 0; m < 2; m++) {
                    mma_bf16(s[m][2 * jp],     qh[m][0], qh[m][1], qh[m][2], qh[m][3], h0, h1);
                    mma_bf16(s[m][2 * jp],     qh[m][0], qh[m][1], qh[m][2], qh[m][3], l0, l1);
                    mma_bf16(s[m][2 * jp],     ql[m][0], ql[m][1], ql[m][2], ql[m][3], h0, h1);
                    mma_bf16(s[m][2 * jp + 1], qh[m][0], qh[m][1], qh[m][2], qh[m][3], h2, h3);
                    mma_bf16(s[m][2 * jp + 1], qh[m][0], qh[m][1], qh[m][2], qh[m][3], l2, l3);
                    mma_bf16(s[m][2 * jp + 1], ql[m][0], ql[m][1], ql[m][2], ql[m][3], h2, h3);
                }
            }
        }

        // ---- mask + scale + online softmax ----
        float mt[4] = {-1e30f, -1e30f, -1e30f, -1e30f};
#pragma unroll
        for (int r = 0; r < 4; r++) {
            const int m = r >> 1, lo2 = (r & 1) * 2;
#pragma unroll
            for (int jn = 0; jn < 8; jn++) {
                const uint32_t word = mw[r][jn >> 2];
                const int bp = (jn & 3) * 8 + 2 * qd;
                float x0 = ((word >> bp) & 1u)       ? s[m][jn][lo2]     * 0.125f : -1e20f;
                float x1 = ((word >> (bp + 1)) & 1u) ? s[m][jn][lo2 + 1] * 0.125f : -1e20f;
                s[m][jn][lo2] = x0; s[m][jn][lo2 + 1] = x1;
                mt[r] = fmaxf(mt[r], fmaxf(x0, x1));
            }
        }
#pragma unroll
        for (int r = 0; r < 4; r++) {
            mt[r] = fmaxf(mt[r], __shfl_xor_sync(0xffffffffu, mt[r], 1));
            mt[r] = fmaxf(mt[r], __shfl_xor_sync(0xffffffffu, mt[r], 2));
        }
        float corr[4];
#pragma unroll
        for (int r = 0; r < 4; r++) {
            const float mn = fmaxf(mx[r], mt[r]);
            corr[r] = __expf(mx[r] - mn);
            mx[r] = mn;
        }
        float rs[4] = {};
#pragma unroll
        for (int r = 0; r < 4; r++) {
            const int m = r >> 1, lo2 = (r & 1) * 2;
#pragma unroll
            for (int jn = 0; jn < 8; jn++) {
                float p0 = __expf(s[m][jn][lo2] - mx[r]);
                float p1 = __expf(s[m][jn][lo2 + 1] - mx[r]);
                s[m][jn][lo2] = p0; s[m][jn][lo2 + 1] = p1;
                rs[r] += p0 + p1;
            }
        }
#pragma unroll
        for (int r = 0; r < 4; r++) {
            rs[r] += __shfl_xor_sync(0xffffffffu, rs[r], 1);
            rs[r] += __shfl_xor_sync(0xffffffffu, rs[r], 2);
            ls[r] = ls[r] * corr[r] + rs[r];
        }
#pragma unroll
        for (int r = 0; r < 4; r++) {
            const int m = r >> 1, lo2 = (r & 1) * 2;
#pragma unroll
            for (int jn = 0; jn < 8; jn++) {
                o[m][jn][lo2]     *= corr[r];
                o[m][jn][lo2 + 1] *= corr[r];
            }
        }

        // ---- MMA2: O += Ph*Vh + Ph*Vl + Pl*Vh ----
#pragma unroll
        for (int kc = 0; kc < 4; kc++) {
            uint32_t ph[2][4], pl[2][4];
#pragma unroll
            for (int m = 0; m < 2; m++) {
                uint2 a0 = split2(s[m][2 * kc][0],     s[m][2 * kc][1]);
                uint2 a1 = split2(s[m][2 * kc][2],     s[m][2 * kc][3]);
                uint2 a2 = split2(s[m][2 * kc + 1][0], s[m][2 * kc + 1][1]);
                uint2 a3 = split2(s[m][2 * kc + 1][2], s[m][2 * kc + 1][3]);
                ph[m][0] = a0.x; ph[m][1] = a1.x; ph[m][2] = a2.x; ph[m][3] = a3.x;
                pl[m][0] = a0.y; pl[m][1] = a1.y; pl[m][2] = a2.y; pl[m][3] = a3.y;
            }
#pragma unroll
            for (int jp = 0; jp < 4; jp++) {
                const uint32_t ad = bufc + (uint32_t)(2 * PLANEB + jp * 16 * ROWB + kc * 32) + offB;
                uint32_t h0, h1, h2, h3, l0, l1, l2, l3;
                ldsm4(h0, h1, h2, h3, ad);
                ldsm4(l0, l1, l2, l3, ad + PLANEB);
#pragma unroll
                for (int m = 0; m < 2; m++) {
                    mma_bf16(o[m][2 * jp],     ph[m][0], ph[m][1], ph[m][2], ph[m][3], h0, h1);
                    mma_bf16(o[m][2 * jp],     ph[m][0], ph[m][1], ph[m][2], ph[m][3], l0, l1);
                    mma_bf16(o[m][2 * jp],     pl[m][0], pl[m][1], pl[m][2], pl[m][3], h0, h1);
                    mma_bf16(o[m][2 * jp + 1], ph[m][0], ph[m][1], ph[m][2], ph[m][3], h2, h3);
                    mma_bf16(o[m][2 * jp + 1], ph[m][0], ph[m][1], ph[m][2], ph[m][3], l2, l3);
                    mma_bf16(o[m][2 * jp + 1], pl[m][0], pl[m][1], pl[m][2], pl[m][3], h2, h3);
                }
            }
        }
        __syncthreads();
    }

    // ---- epilogue: unnormalized partials + (m, l) ----
    float*  OP = half ? g_OP1 : g_OP0;
    float2* ML = half ? g_ML1 : g_ML0;
#pragma unroll
    for (int r = 0; r < 4; r++) {
        const int m = r >> 1, lo2 = (r & 1) * 2;
        const size_t row = (size_t)bh * SLEN + q0 + 32 * w + g + 8 * r;
        float* Ob = OP + row * DH;
#pragma unroll
        for (int jn = 0; jn < 8; jn++)
            *reinterpret_cast<float2*>(Ob + 8 * jn + 2 * qd) =
                make_float2(o[m][jn][lo2], o[m][jn][lo2 + 1]);
        if (qd == 0) ML[row] = make_float2(mx[r], ls[r]);
    }
}

// ---------------- combine kernel ----------------

__global__ void __launch_bounds__(256)
combine_kernel(float* __restrict__ O)
{
    const int t   = blockIdx.x * 256 + threadIdx.x;
    const int row = t >> 4;
    const int seg = t & 15;
    float2 a = g_ML0[row], b = g_ML1[row];
    float m  = fmaxf(a.x, b.x);
    float e0 = __expf(a.x - m), e1 = __expf(b.x - m);
    float inv = 1.0f / (a.y * e0 + b.y * e1);
    float4 x = reinterpret_cast<const float4*>(g_OP0)[(size_t)row * 16 + seg];
    float4 y = reinterpret_cast<const float4*>(g_OP1)[(size_t)row * 16 + seg];
    float4 r = make_float4((x.x * e0 + y.x * e1) * inv,
                           (x.y * e0 + y.y * e1) * inv,
                           (x.z * e0 + y.z * e1) * inv,
                           (x.w * e0 + y.w * e1) * inv);
    reinterpret_cast<float4*>(O)[(size_t)row * 16 + seg] = r;
}

extern "C" void kernel_launch(void* const* d_in, const int* in_sizes, int n_in,
                              void* d_out, int out_size)
{
    const float* Q    = (const float*)d_in[0];
    const float* K    = (const float*)d_in[1];
    const float* V    = (const float*)d_in[2];
    const int*   mask = (const int*)d_in[3];
    float*       O    = (float*)d_out;

    prep_qk<<<NELEM / 1024, 256>>>(Q, K);
    prep_vt<<<dim3(SLEN / 64, BATCH * HN), 256>>>(V);
    prep_mask<<<(BATCH * SLEN * (SLEN / 32)) / 8, 256>>>(mask);

    cudaFuncSetAttribute(attn_mma_kernel,
                         cudaFuncAttributeMaxDynamicSharedMemorySize, SMEM_BYTES);
    dim3 grid(SLEN / BQ, HN, BATCH * NSPLIT);   // 16 x 12 x 4 = 768 CTAs
    attn_mma_kernel<<<grid, NTH, SMEM_BYTES>>>();

    combine_kernel<<<(NROWS * 16) / 256, 256>>>(O);
}